// round 15
// baseline (speedup 1.0000x reference)
#include <cuda_runtime.h>
#include <cstdint>
#include <math.h>

// Problem constants
#define BB   8
#define TT   1024
#define HH   768
#define NH   12
#define HS   64
#define H3   2304          // 3*H
#define MROWS (BB*TT)      // 8192

// Scratch (device globals — no allocations allowed)
__device__ float g_qkv[(size_t)MROWS * H3];   // [8192, 2304]
__device__ float g_att[(size_t)MROWS * HH];   // [8192, 768] (tf32-rounded by attn epilogue)
__device__ float g_xr [(size_t)MROWS * HH];   // tf32-rounded x
__device__ float g_war[(size_t)HH * H3];      // tf32-rounded W_attn
__device__ float g_wpr[(size_t)HH * HH];      // tf32-rounded W_proj

// ---------------------------------------------------------------------------
// tf32 / cp.async helpers (arch-generic PTX; NO tcgen05 — harness lowers via
// compute_103 which rejects all sm_103a-gated instructions)
// ---------------------------------------------------------------------------
__device__ __forceinline__ float to_tf32(float x) {
    float y;
    asm("cvt.rna.tf32.f32 %0, %1;" : "=f"(y) : "f"(x));
    return y;
}

__device__ __forceinline__ void mma1688(float* d, const uint32_t* a, const uint32_t* b) {
    asm volatile(
        "mma.sync.aligned.m16n8k8.row.col.f32.tf32.tf32.f32 "
        "{%0,%1,%2,%3}, {%4,%5,%6,%7}, {%8,%9}, {%0,%1,%2,%3};"
        : "+f"(d[0]), "+f"(d[1]), "+f"(d[2]), "+f"(d[3])
        : "r"(a[0]), "r"(a[1]), "r"(a[2]), "r"(a[3]),
          "r"(b[0]), "r"(b[1]));
}

__device__ __forceinline__ uint32_t smem_u32(const void* p) {
    uint32_t a;
    asm("{ .reg .u64 t; cvta.to.shared.u64 t, %1; cvt.u32.u64 %0, t; }"
        : "=r"(a) : "l"(p));
    return a;
}
__device__ __forceinline__ void cp_async16(uint32_t dst, const void* src) {
    asm volatile("cp.async.cg.shared.global [%0], [%1], 16;"
                 :: "r"(dst), "l"(src) : "memory");
}
#define CP_COMMIT()  asm volatile("cp.async.commit_group;" ::: "memory")
#define CP_WAIT1()   asm volatile("cp.async.wait_group 1;" ::: "memory")
#define CP_WAIT0()   asm volatile("cp.async.wait_group 0;" ::: "memory")

// ---------------------------------------------------------------------------
// Elementwise tf32 rounding pass (grid-stride float4). ~HBM-rate, <10us total.
// ---------------------------------------------------------------------------
__global__ __launch_bounds__(256) void round_tf32_kernel(
    const float* __restrict__ in, float* __restrict__ out, int n4)
{
    int i = blockIdx.x * blockDim.x + threadIdx.x;
    int stride = gridDim.x * blockDim.x;
    for (; i < n4; i += stride) {
        float4 v = ((const float4*)in)[i];
        float4 w;
        w.x = to_tf32(v.x); w.y = to_tf32(v.y);
        w.z = to_tf32(v.z); w.w = to_tf32(v.w);
        ((float4*)out)[i] = w;
    }
}

// ===========================================================================
// Warp-MMA tf32 GEMM with bias: C[M,N] = A[M,K] @ B[K,N] + bias[N]
// A and B must already be tf32-valued fp32 (pre-rounded) -> NO cvt anywhere.
// BM=128, BN=128, BK=32, 256 threads = 8 warps (4 m x 2 n), warp tile 32x64.
// 3-STAGE cp.async pipeline: tile kc is waited on 2 iterations after issue,
// so the wait_group<=1 is pre-satisfied and copy latency is fully hidden.
// Bank-conflict-free fragment layouts:
//   As[m][k] pitch 36 (mod 32 = 4): A-frag bank = 4g+tig -> distinct.
//   Bs[k][n] pitch 136 (mod 32 = 8): B-frag bank = 8tig+g -> distinct.
// ===========================================================================
#define AP 36    // As row pitch (floats): [128 m][32 k]
#define BP 136   // Bs row pitch (floats): [32 k][128 n]
#define GEMM_BUF (128 * AP + 32 * BP)                 // floats per stage: 8960
#define NSTAGE 3
#define GEMM_SMEM (NSTAGE * GEMM_BUF * sizeof(float)) // 107520 bytes

__global__ __launch_bounds__(256, 2) void gemm_mma_kernel(
    const float* __restrict__ A, const float* __restrict__ B,
    const float* __restrict__ bias, float* __restrict__ C,
    int M, int N, int K)
{
    extern __shared__ float smem[];

    const int tid = threadIdx.x;
    const int wid = tid >> 5;
    const int lane = tid & 31;
    const int g   = lane >> 2;
    const int tig = lane & 3;
    const int wm = wid & 3;
    const int wn = wid >> 2;
    const int bm = blockIdx.y * 128;
    const int bn = blockIdx.x * 128;

    const int a_m  = tid >> 3;      // 0..31 (+32 per i)
    const int a_c4 = tid & 7;       // float4 index within 32-float k-row
    const int b_k  = tid >> 5;      // 0..7 (+8 per i)
    const int b_n4 = lane;          // 0..31 float4 index

    // Per-thread cp.async smem dst addresses (byte addresses), per stage
    uint32_t a_dst[NSTAGE], b_dst[NSTAGE];
    #pragma unroll
    for (int s = 0; s < NSTAGE; s++) {
        a_dst[s] = smem_u32(smem + s * GEMM_BUF + a_m * AP + a_c4 * 4);
        b_dst[s] = smem_u32(smem + s * GEMM_BUF + 128 * AP + b_k * BP + b_n4 * 4);
    }
    // Incrementally advanced source pointers
    const float* asrc = A + (size_t)(bm + a_m) * K + a_c4 * 4;
    const float* bsrc = B + (size_t)b_k * N + bn + b_n4 * 4;
    const size_t aKstride = (size_t)32 * K;   // per-i row stride for A copies
    const size_t bNstride = (size_t)8 * N;    // per-i row stride for B copies

    float d[2][8][4];
    #pragma unroll
    for (int mt = 0; mt < 2; mt++)
        #pragma unroll
        for (int nt = 0; nt < 8; nt++)
            #pragma unroll
            for (int r = 0; r < 4; r++) d[mt][nt][r] = 0.f;

    const int nit = K >> 5;

    // ---- Prologue: issue tiles 0 and 1 into stages 0 and 1 ----
    #pragma unroll
    for (int s = 0; s < 2; s++) {
        #pragma unroll
        for (int i = 0; i < 4; i++)
            cp_async16(a_dst[s] + i * (32 * AP * 4), asrc + i * aKstride);
        #pragma unroll
        for (int i = 0; i < 4; i++)
            cp_async16(b_dst[s] + i * (8 * BP * 4), bsrc + i * bNstride);
        CP_COMMIT();
        asrc += 32;
        bsrc += (size_t)32 * N;
    }

    int cur = 0;                    // stage holding tile kc
    for (int kc = 0; kc < nit; kc++) {
        // ---- Tile kc was issued 2 iterations ago: wait (pre-satisfied), sync ----
        CP_WAIT1();                 // <=1 outstanding group => tile kc complete
        __syncthreads();            // all warps: tile kc visible; stage (kc+2)%3 free

        // ---- Issue tile kc+2 into the stage freed last iteration ----
        if (kc + 2 < nit) {
            const int nxt = (cur + 2 >= NSTAGE) ? cur + 2 - NSTAGE : cur + 2;
            #pragma unroll
            for (int i = 0; i < 4; i++)
                cp_async16(a_dst[nxt] + i * (32 * AP * 4), asrc + i * aKstride);
            #pragma unroll
            for (int i = 0; i < 4; i++)
                cp_async16(b_dst[nxt] + i * (8 * BP * 4), bsrc + i * bNstride);
            CP_COMMIT();
            asrc += 32;
            bsrc += (size_t)32 * N;
        } else {
            CP_COMMIT();            // keep group accounting uniform for CP_WAIT1
        }

        // ---- Compute on current stage (pure LDS + HMMA; data already tf32) ----
        const float* As = smem + cur * GEMM_BUF;
        const float* Bs = As + 128 * AP;
        #pragma unroll
        for (int ks = 0; ks < 4; ks++) {
            const int k0 = ks * 8;
            uint32_t af[2][4];
            #pragma unroll
            for (int mt = 0; mt < 2; mt++) {
                int mrow = wm * 32 + mt * 16 + g;
                af[mt][0] = __float_as_uint(As[mrow * AP + k0 + tig]);
                af[mt][1] = __float_as_uint(As[(mrow + 8) * AP + k0 + tig]);
                af[mt][2] = __float_as_uint(As[mrow * AP + k0 + tig + 4]);
                af[mt][3] = __float_as_uint(As[(mrow + 8) * AP + k0 + tig + 4]);
            }
            uint32_t bf[8][2];
            #pragma unroll
            for (int nt = 0; nt < 8; nt++) {
                int ncol = wn * 64 + nt * 8 + g;
                bf[nt][0] = __float_as_uint(Bs[(k0 + tig) * BP + ncol]);
                bf[nt][1] = __float_as_uint(Bs[(k0 + tig + 4) * BP + ncol]);
            }
            #pragma unroll
            for (int mt = 0; mt < 2; mt++)
                #pragma unroll
                for (int nt = 0; nt < 8; nt++)
                    mma1688(d[mt][nt], af[mt], bf[nt]);
        }

        cur = (cur + 1 >= NSTAGE) ? 0 : cur + 1;
    }

    // Epilogue: bias add + store
    #pragma unroll
    for (int mt = 0; mt < 2; mt++) {
        int r0 = bm + wm * 32 + mt * 16 + g;
        #pragma unroll
        for (int nt = 0; nt < 8; nt++) {
            int c0 = bn + wn * 64 + nt * 8 + tig * 2;
            float bx = bias[c0], by = bias[c0 + 1];
            float2 o0 = make_float2(d[mt][nt][0] + bx, d[mt][nt][1] + by);
            float2 o1 = make_float2(d[mt][nt][2] + bx, d[mt][nt][3] + by);
            *(float2*)(C + (size_t)r0 * N + c0)       = o0;
            *(float2*)(C + (size_t)(r0 + 8) * N + c0) = o1;
        }
    }
}

// ===========================================================================
// Causal flash attention via tf32 mma.sync.  (unchanged — R10-proven; epilogue
// writes tf32-rounded output so the proj GEMM needs no cvt.)
// Block = 128 threads (4 warps), Q tile = 64 rows (16/warp), K/V tile = 64.
// grid = (T/64, NH, B). Only kt <= qt tiles; diagonal tile element-masked.
//   Ks pitch 68: B-frag banks 4g+tig (conflict-free); Q stages through Ks.
//   Vs pitch 72: B-frag banks 8tig+g (conflict-free).
// P converted C-layout -> A-layout in-register via shfl (no smem round trip).
// ===========================================================================
#define KP 68
#define VP 72

__global__ __launch_bounds__(128, 3) void attn_mma_kernel(
    const float* __restrict__ qkv, float* __restrict__ att)
{
    __shared__ float Ks[64][KP];   // K tile; also stages Q at start
    __shared__ float Vs[64][VP];   // V tile

    const int tid  = threadIdx.x;
    const int wid  = tid >> 5;
    const int lane = tid & 31;
    const int g    = lane >> 2;
    const int tig  = lane & 3;
    const int b    = blockIdx.z;
    const int h    = blockIdx.y;
    const int qt   = blockIdx.x;        // q tile index 0..15
    const int qs   = qt * 64;

    // ---- Stage Q tile (scaled by 1/8, tf32-rounded) into Ks buffer ----
    {
        const float* qb = qkv + (size_t)(b * TT + qs) * H3 + h * HS;
        #pragma unroll
        for (int i = 0; i < 8; i++) {
            int idx = tid + i * 128;
            int r = idx >> 4, c4 = idx & 15;
            float4 v = *(const float4*)(qb + (size_t)r * H3 + c4 * 4);
            float4 w;
            w.x = to_tf32(v.x * 0.125f); w.y = to_tf32(v.y * 0.125f);
            w.z = to_tf32(v.z * 0.125f); w.w = to_tf32(v.w * 0.125f);
            *(float4*)&Ks[r][c4 * 4] = w;
        }
    }
    __syncthreads();

    // ---- Extract Q fragments to registers (A-layout, m16k8 per k-step) ----
    uint32_t af[8][4];
    {
        const int r0 = wid * 16 + g;
        #pragma unroll
        for (int ks = 0; ks < 8; ks++) {
            af[ks][0] = __float_as_uint(Ks[r0][ks * 8 + tig]);
            af[ks][1] = __float_as_uint(Ks[r0 + 8][ks * 8 + tig]);
            af[ks][2] = __float_as_uint(Ks[r0][ks * 8 + tig + 4]);
            af[ks][3] = __float_as_uint(Ks[r0 + 8][ks * 8 + tig + 4]);
        }
    }

    float O[8][4];
    #pragma unroll
    for (int nt = 0; nt < 8; nt++)
        #pragma unroll
        for (int r = 0; r < 4; r++) O[nt][r] = 0.f;
    float m0 = -INFINITY, m1 = -INFINITY, l0 = 0.f, l1 = 0.f;
    const int row0 = qs + wid * 16 + g;     // global q rows this thread owns
    const int row1 = row0 + 8;

    const int s0l = (lane & ~3) | (tig >> 1);   // shfl source lanes for P conversion
    const int s1l = s0l + 2;
    const bool todd = (tig & 1);

    for (int kt = 0; kt <= qt; kt++) {
        __syncthreads();    // prior compute / Q extraction done before overwrite
        // ---- Stage K and V tiles (tf32-rounded) ----
        const float* kb = qkv + (size_t)(b * TT + kt * 64) * H3 + HH + h * HS;
        const float* vb = kb + HH;
        #pragma unroll
        for (int i = 0; i < 8; i++) {
            int idx = tid + i * 128;
            int r = idx >> 4, c4 = idx & 15;
            float4 v = *(const float4*)(kb + (size_t)r * H3 + c4 * 4);
            float4 w;
            w.x = to_tf32(v.x); w.y = to_tf32(v.y);
            w.z = to_tf32(v.z); w.w = to_tf32(v.w);
            *(float4*)&Ks[r][c4 * 4] = w;
            float4 u = *(const float4*)(vb + (size_t)r * H3 + c4 * 4);
            float4 z;
            z.x = to_tf32(u.x); z.y = to_tf32(u.y);
            z.z = to_tf32(u.z); z.w = to_tf32(u.w);
            *(float4*)&Vs[r][c4 * 4] = z;
        }
        __syncthreads();

        // ---- S = Q @ K^T  (16 rows x 64 keys per warp) ----
        float S[8][4];
        #pragma unroll
        for (int nt = 0; nt < 8; nt++)
            #pragma unroll
            for (int r = 0; r < 4; r++) S[nt][r] = 0.f;
        #pragma unroll
        for (int ks = 0; ks < 8; ks++) {
            #pragma unroll
            for (int nt = 0; nt < 8; nt++) {
                uint32_t bf[2];
                bf[0] = __float_as_uint(Ks[nt * 8 + g][ks * 8 + tig]);
                bf[1] = __float_as_uint(Ks[nt * 8 + g][ks * 8 + tig + 4]);
                mma1688(S[nt], af[ks], bf);
            }
        }

        // ---- Causal mask (diagonal tile only) ----
        if (kt == qt) {
            #pragma unroll
            for (int nt = 0; nt < 8; nt++) {
                int c0 = kt * 64 + nt * 8 + 2 * tig;
                if (c0     > row0) S[nt][0] = -INFINITY;
                if (c0 + 1 > row0) S[nt][1] = -INFINITY;
                if (c0     > row1) S[nt][2] = -INFINITY;
                if (c0 + 1 > row1) S[nt][3] = -INFINITY;
            }
        }

        // ---- Online softmax ----
        float tm0 = -INFINITY, tm1 = -INFINITY;
        #pragma unroll
        for (int nt = 0; nt < 8; nt++) {
            tm0 = fmaxf(tm0, fmaxf(S[nt][0], S[nt][1]));
            tm1 = fmaxf(tm1, fmaxf(S[nt][2], S[nt][3]));
        }
        tm0 = fmaxf(tm0, __shfl_xor_sync(0xffffffffu, tm0, 1));
        tm0 = fmaxf(tm0, __shfl_xor_sync(0xffffffffu, tm0, 2));
        tm1 = fmaxf(tm1, __shfl_xor_sync(0xffffffffu, tm1, 1));
        tm1 = fmaxf(tm1, __shfl_xor_sync(0xffffffffu, tm1, 2));

        float mn0 = fmaxf(m0, tm0), mn1 = fmaxf(m1, tm1);
        float al0 = __expf(m0 - mn0), al1 = __expf(m1 - mn1);
        m0 = mn0; m1 = mn1;

        float rs0 = 0.f, rs1 = 0.f;
        uint32_t P[8][4];
        #pragma unroll
        for (int nt = 0; nt < 8; nt++) {
            float p0 = __expf(S[nt][0] - mn0);
            float p1 = __expf(S[nt][1] - mn0);
            float p2 = __expf(S[nt][2] - mn1);
            float p3 = __expf(S[nt][3] - mn1);
            rs0 += p0 + p1;
            rs1 += p2 + p3;
            P[nt][0] = __float_as_uint(to_tf32(p0));
            P[nt][1] = __float_as_uint(to_tf32(p1));
            P[nt][2] = __float_as_uint(to_tf32(p2));
            P[nt][3] = __float_as_uint(to_tf32(p3));
        }
        rs0 += __shfl_xor_sync(0xffffffffu, rs0, 1);
        rs0 += __shfl_xor_sync(0xffffffffu, rs0, 2);
        rs1 += __shfl_xor_sync(0xffffffffu, rs1, 1);
        rs1 += __shfl_xor_sync(0xffffffffu, rs1, 2);
        l0 = l0 * al0 + rs0;
        l1 = l1 * al1 + rs1;

        #pragma unroll
        for (int nt = 0; nt < 8; nt++) {
            O[nt][0] *= al0; O[nt][1] *= al0;
            O[nt][2] *= al1; O[nt][3] *= al1;
        }

        // ---- O += P @ V ----
        #pragma unroll
        for (int ks = 0; ks < 8; ks++) {
            // Convert P C-layout (cols 2tig,2tig+1) -> A-layout (cols tig,tig+4)
            uint32_t t00 = __shfl_sync(0xffffffffu, P[ks][0], s0l);
            uint32_t t01 = __shfl_sync(0xffffffffu, P[ks][1], s0l);
            uint32_t t10 = __shfl_sync(0xffffffffu, P[ks][2], s0l);
            uint32_t t11 = __shfl_sync(0xffffffffu, P[ks][3], s0l);
            uint32_t u00 = __shfl_sync(0xffffffffu, P[ks][0], s1l);
            uint32_t u01 = __shfl_sync(0xffffffffu, P[ks][1], s1l);
            uint32_t u10 = __shfl_sync(0xffffffffu, P[ks][2], s1l);
            uint32_t u11 = __shfl_sync(0xffffffffu, P[ks][3], s1l);
            uint32_t a[4];
            a[0] = todd ? t01 : t00;   // (row g,   col tig)
            a[1] = todd ? t11 : t10;   // (row g+8, col tig)
            a[2] = todd ? u01 : u00;   // (row g,   col tig+4)
            a[3] = todd ? u11 : u10;   // (row g+8, col tig+4)
            #pragma unroll
            for (int nt = 0; nt < 8; nt++) {
                uint32_t bf[2];
                bf[0] = __float_as_uint(Vs[ks * 8 + tig][nt * 8 + g]);
                bf[1] = __float_as_uint(Vs[ks * 8 + tig + 4][nt * 8 + g]);
                mma1688(O[nt], a, bf);
            }
        }
    }

    // ---- Epilogue: normalize, tf32-round (for proj GEMM), store ----
    const float inv0 = 1.f / l0;
    const float inv1 = 1.f / l1;
    float* o0p = att + (size_t)(b * TT + row0) * HH + h * HS;
    float* o1p = att + (size_t)(b * TT + row1) * HH + h * HS;
    #pragma unroll
    for (int nt = 0; nt < 8; nt++) {
        int c = nt * 8 + 2 * tig;
        *(float2*)(o0p + c) = make_float2(to_tf32(O[nt][0] * inv0), to_tf32(O[nt][1] * inv0));
        *(float2*)(o1p + c) = make_float2(to_tf32(O[nt][2] * inv1), to_tf32(O[nt][3] * inv1));
    }
}

// ---------------------------------------------------------------------------
// Launch
// ---------------------------------------------------------------------------
extern "C" void kernel_launch(void* const* d_in, const int* in_sizes, int n_in,
                              void* d_out, int out_size)
{
    const float* x      = (const float*)d_in[0];   // [8,1024,768]
    const float* W_attn = (const float*)d_in[1];   // [768,2304]
    const float* b_attn = (const float*)d_in[2];   // [2304]
    const float* W_proj = (const float*)d_in[3];   // [768,768]
    const float* b_proj = (const float*)d_in[4];   // [768]
    float* out = (float*)d_out;                    // [8,1024,768]

    float* qkv;  cudaGetSymbolAddress((void**)&qkv,  g_qkv);
    float* attb; cudaGetSymbolAddress((void**)&attb, g_att);
    float* xr;   cudaGetSymbolAddress((void**)&xr,   g_xr);
    float* war;  cudaGetSymbolAddress((void**)&war,  g_war);
    float* wpr;  cudaGetSymbolAddress((void**)&wpr,  g_wpr);

    cudaFuncSetAttribute(gemm_mma_kernel,
                         cudaFuncAttributeMaxDynamicSharedMemorySize, GEMM_SMEM);

    // 0) Pre-round operands to tf32-valued fp32 (~35MB traffic, <10us total)
    round_tf32_kernel<<<592, 256>>>(x,      xr,  (MROWS * HH) / 4);
    round_tf32_kernel<<<592, 256>>>(W_attn, war, (HH * H3) / 4);
    round_tf32_kernel<<<592, 256>>>(W_proj, wpr, (HH * HH) / 4);

    // 1) QKV projection: [8192,768] @ [768,2304] + b -> g_qkv  (tf32 mma.sync)
    {
        dim3 grid(H3 / 128, MROWS / 128);
        gemm_mma_kernel<<<grid, 256, GEMM_SMEM>>>(xr, war, b_attn, qkv, MROWS, H3, HH);
    }
    // 2) Causal attention (tf32 mma.sync flash) -> g_att (tf32-rounded output)
    {
        dim3 grid(TT / 64, NH, BB);
        attn_mma_kernel<<<grid, 128>>>(qkv, attb);
    }
    // 3) Output projection: [8192,768] @ [768,768] + b -> out  (tf32 mma.sync)
    {
        dim3 grid(HH / 128, MROWS / 128);
        gemm_mma_kernel<<<grid, 256, GEMM_SMEM>>>(attb, wpr, b_proj, out, MROWS, HH, HH);
    }
}

// round 16
// speedup vs baseline: 1.2504x; 1.2504x over previous
#include <cuda_runtime.h>
#include <cuda_fp16.h>
#include <cstdint>
#include <math.h>

// Problem constants
#define BB   8
#define TT   1024
#define HH   768
#define NH   12
#define HS   64
#define H3   2304          // 3*H
#define MROWS (BB*TT)      // 8192

// Scratch (device globals — no allocations allowed)
__device__ __half g_qkvh[(size_t)MROWS * H3];  // fp16 qkv
__device__ __half g_atth[(size_t)MROWS * HH];  // fp16 attention output
__device__ __half g_xh [(size_t)MROWS * HH];   // fp16 x
__device__ __half g_wah[(size_t)HH * H3];      // fp16 W_attn
__device__ __half g_wph[(size_t)HH * HH];      // fp16 W_proj

// ---------------------------------------------------------------------------
// Helpers (arch-generic PTX only — compute_103 rejects sm_103a-gated instrs)
// ---------------------------------------------------------------------------
__device__ __forceinline__ uint32_t smem_u32(const void* p) {
    uint32_t a;
    asm("{ .reg .u64 t; cvta.to.shared.u64 t, %1; cvt.u32.u64 %0, t; }"
        : "=r"(a) : "l"(p));
    return a;
}
__device__ __forceinline__ void cp_async16(uint32_t dst, const void* src) {
    asm volatile("cp.async.cg.shared.global [%0], [%1], 16;"
                 :: "r"(dst), "l"(src) : "memory");
}
#define CP_COMMIT()  asm volatile("cp.async.commit_group;" ::: "memory")
#define CP_WAIT1()   asm volatile("cp.async.wait_group 1;" ::: "memory")
#define CP_WAIT0()   asm volatile("cp.async.wait_group 0;" ::: "memory")

__device__ __forceinline__ void ldsm_x4(uint32_t* r, uint32_t addr) {
    asm volatile("ldmatrix.sync.aligned.m8n8.x4.shared.b16 {%0,%1,%2,%3}, [%4];"
                 : "=r"(r[0]), "=r"(r[1]), "=r"(r[2]), "=r"(r[3]) : "r"(addr));
}
__device__ __forceinline__ void ldsm_x4_t(uint32_t* r, uint32_t addr) {
    asm volatile("ldmatrix.sync.aligned.m8n8.x4.trans.shared.b16 {%0,%1,%2,%3}, [%4];"
                 : "=r"(r[0]), "=r"(r[1]), "=r"(r[2]), "=r"(r[3]) : "r"(addr));
}
__device__ __forceinline__ void mma16816(float* d, const uint32_t* a, const uint32_t* b) {
    asm volatile(
        "mma.sync.aligned.m16n8k16.row.col.f32.f16.f16.f32 "
        "{%0,%1,%2,%3}, {%4,%5,%6,%7}, {%8,%9}, {%0,%1,%2,%3};"
        : "+f"(d[0]), "+f"(d[1]), "+f"(d[2]), "+f"(d[3])
        : "r"(a[0]), "r"(a[1]), "r"(a[2]), "r"(a[3]),
          "r"(b[0]), "r"(b[1]));
}
__device__ __forceinline__ uint32_t pack_h2(float lo, float hi) {
    __half2 h = __floats2half2_rn(lo, hi);
    return *(uint32_t*)&h;
}

// ---------------------------------------------------------------------------
// Elementwise f32 -> f16 conversion (grid-stride, 8 elems/thread-step)
// ---------------------------------------------------------------------------
__global__ __launch_bounds__(256) void f32_to_f16_kernel(
    const float* __restrict__ in, __half* __restrict__ out, int n8)
{
    int i = blockIdx.x * blockDim.x + threadIdx.x;
    int stride = gridDim.x * blockDim.x;
    for (; i < n8; i += stride) {
        float4 v0 = ((const float4*)in)[2 * i];
        float4 v1 = ((const float4*)in)[2 * i + 1];
        uint4 o;
        o.x = pack_h2(v0.x, v0.y);
        o.y = pack_h2(v0.z, v0.w);
        o.z = pack_h2(v1.x, v1.y);
        o.w = pack_h2(v1.z, v1.w);
        ((uint4*)out)[i] = o;
    }
}

// ===========================================================================
// fp16 warp-MMA GEMM with bias: C[M,N] = A[M,K] @ B[K,N] + bias[N]
// A,B fp16; accum f32. BM=128, BN=128, BK=32, 256 thr = 8 warps (4m x 2n),
// warp tile 32x64, m16n8k16. 3-stage cp.async pipeline.
// Smem (bytes): As 128 rows x 80 (64 data + 16 pad), Bs 32 rows x 272
// (256 data + 16 pad). ldmatrix row-addresses bank-conflict-free for both.
// out_half: 1 -> write __half C, 0 -> float C.
// ===========================================================================
#define A_PITCH 80
#define B_PITCH 272
#define A_BYTES (128 * A_PITCH)                 // 10240
#define STAGE_BYTES (A_BYTES + 32 * B_PITCH)    // 18944
#define NSTAGE 3
#define GEMM_SMEM (NSTAGE * STAGE_BYTES)        // 56832

__global__ __launch_bounds__(256, 2) void gemm_f16_kernel(
    const __half* __restrict__ A, const __half* __restrict__ B,
    const float* __restrict__ bias, void* __restrict__ Cv,
    int M, int N, int K, int out_half)
{
    extern __shared__ __align__(16) char smem[];

    const int tid = threadIdx.x;
    const int wid = tid >> 5;
    const int lane = tid & 31;
    const int g    = lane >> 2;
    const int tig  = lane & 3;
    const int matid = lane >> 3;
    const int lr    = lane & 7;
    const int wm = wid & 3;
    const int wn = wid >> 2;
    const int bm = blockIdx.y * 128;
    const int bn = blockIdx.x * 128;

    const uint32_t sbase = smem_u32(smem);

    // cp.async destination offsets (per thread)
    const uint32_t a_cp = (uint32_t)((tid >> 2) * A_PITCH + (tid & 3) * 16);
    const uint32_t b_cp = (uint32_t)A_BYTES + (tid >> 4) * B_PITCH + (tid & 15) * 16;

    // Incrementally advanced gmem sources (half units)
    const __half* asrc = A + (size_t)(bm + (tid >> 2)) * K + (tid & 3) * 8;
    const __half* bsrc = B + (size_t)(tid >> 4) * N + bn + (tid & 15) * 8;
    const size_t aRow = (size_t)64 * K;   // +64 rows
    const size_t bRow = (size_t)16 * N;   // +16 k-rows

    // ldmatrix per-lane offsets
    const uint32_t a_lds = (uint32_t)((wm * 32 + (matid & 1) * 8 + lr) * A_PITCH
                                      + (matid >> 1) * 16);
    const uint32_t b_lds = (uint32_t)A_BYTES
                         + ((matid & 1) * 8 + lr) * B_PITCH
                         + (wn * 64 + (matid >> 1) * 8) * 2;

    float d[2][8][4];
    #pragma unroll
    for (int mt = 0; mt < 2; mt++)
        #pragma unroll
        for (int nt = 0; nt < 8; nt++)
            #pragma unroll
            for (int r = 0; r < 4; r++) d[mt][nt][r] = 0.f;

    const int nit = K >> 5;

    // Prologue: issue tiles 0,1
    #pragma unroll
    for (int s = 0; s < 2; s++) {
        uint32_t sb = sbase + s * STAGE_BYTES;
        #pragma unroll
        for (int i = 0; i < 2; i++)
            cp_async16(sb + a_cp + i * (64 * A_PITCH), asrc + i * aRow);
        #pragma unroll
        for (int i = 0; i < 2; i++)
            cp_async16(sb + b_cp + i * (16 * B_PITCH), bsrc + i * bRow);
        CP_COMMIT();
        asrc += 32;
        bsrc += (size_t)32 * N;
    }

    int cur = 0;
    for (int kc = 0; kc < nit; kc++) {
        CP_WAIT1();          // tile kc (issued 2 iters ago) complete
        __syncthreads();

        if (kc + 2 < nit) {
            const int nxt = (cur + 2 >= NSTAGE) ? cur + 2 - NSTAGE : cur + 2;
            uint32_t sb = sbase + nxt * STAGE_BYTES;
            #pragma unroll
            for (int i = 0; i < 2; i++)
                cp_async16(sb + a_cp + i * (64 * A_PITCH), asrc + i * aRow);
            #pragma unroll
            for (int i = 0; i < 2; i++)
                cp_async16(sb + b_cp + i * (16 * B_PITCH), bsrc + i * bRow);
            CP_COMMIT();
            asrc += 32;
            bsrc += (size_t)32 * N;
        } else {
            CP_COMMIT();     // uniform group accounting for CP_WAIT1
        }

        const uint32_t sb = sbase + cur * STAGE_BYTES;
        #pragma unroll
        for (int ks = 0; ks < 2; ks++) {
            uint32_t af[2][4];
            #pragma unroll
            for (int mt = 0; mt < 2; mt++)
                ldsm_x4(af[mt], sb + a_lds + mt * (16 * A_PITCH) + ks * 32);
            uint32_t bf[8][2];
            #pragma unroll
            for (int np = 0; np < 4; np++) {
                uint32_t t[4];
                ldsm_x4_t(t, sb + b_lds + ks * (16 * B_PITCH) + np * 32);
                bf[2 * np][0] = t[0]; bf[2 * np][1] = t[1];
                bf[2 * np + 1][0] = t[2]; bf[2 * np + 1][1] = t[3];
            }
            #pragma unroll
            for (int mt = 0; mt < 2; mt++)
                #pragma unroll
                for (int nt = 0; nt < 8; nt++)
                    mma16816(d[mt][nt], af[mt], bf[nt]);
        }

        cur = (cur + 1 >= NSTAGE) ? 0 : cur + 1;
    }

    // Epilogue: bias add + store (f16 or f32)
    #pragma unroll
    for (int mt = 0; mt < 2; mt++) {
        int r0 = bm + wm * 32 + mt * 16 + g;
        #pragma unroll
        for (int nt = 0; nt < 8; nt++) {
            int c0 = bn + wn * 64 + nt * 8 + tig * 2;
            float bx = bias[c0], by = bias[c0 + 1];
            float o00 = d[mt][nt][0] + bx, o01 = d[mt][nt][1] + by;
            float o10 = d[mt][nt][2] + bx, o11 = d[mt][nt][3] + by;
            if (out_half) {
                __half* C = (__half*)Cv;
                *(uint32_t*)(C + (size_t)r0 * N + c0)       = pack_h2(o00, o01);
                *(uint32_t*)(C + (size_t)(r0 + 8) * N + c0) = pack_h2(o10, o11);
            } else {
                float* C = (float*)Cv;
                *(float2*)(C + (size_t)r0 * N + c0)       = make_float2(o00, o01);
                *(float2*)(C + (size_t)(r0 + 8) * N + c0) = make_float2(o10, o11);
            }
        }
    }
}

// ===========================================================================
// Causal flash attention, fp16 mma (m16n8k16) + ldmatrix.
// Block = 128 thr (4 warps), Q tile 64 rows (16/warp), K/V tile 64 keys.
// grid (T/64, NH, B); kt <= qt only; diagonal element-masked.
// qkv is fp16. Scale 1/8 applied to S in f32 (not to Q). K/V double-buffered
// via cp.async. Smem rows pitch 144B (128 data + 16 pad) -> ldmatrix
// conflict-free. P C-frag packs directly into A-frag (no shfl).
// ===========================================================================
#define QKV_PITCH 144

__global__ __launch_bounds__(128, 3) void attn_f16_kernel(
    const __half* __restrict__ qkv, __half* __restrict__ att)
{
    __shared__ __align__(16) __half KV[2][2][64 * 72];  // [stage][K/V][row*72]

    const int tid  = threadIdx.x;
    const int wid  = tid >> 5;
    const int lane = tid & 31;
    const int g    = lane >> 2;
    const int tig  = lane & 3;
    const int matid = lane >> 3;
    const int lr    = lane & 7;
    const int b    = blockIdx.z;
    const int h    = blockIdx.y;
    const int qt   = blockIdx.x;
    const int qs   = qt * 64;

    // ---- Stage Q tile into KV[0][0] (plain copies; fp16 already) ----
    {
        const __half* qb = qkv + (size_t)(b * TT + qs) * H3 + h * HS;
        uint32_t qd = smem_u32(KV[0][0]);
        #pragma unroll
        for (int i = 0; i < 4; i++) {
            int idx = tid + i * 128;
            int r = idx >> 3, c = idx & 7;
            *(uint4*)((char*)KV[0][0] + r * QKV_PITCH + c * 16) =
                *(const uint4*)(qb + (size_t)r * H3 + c * 8);
        }
        (void)qd;
    }
    __syncthreads();

    // ---- Q fragments (A-layout m16k16, 4 k-steps over 64 dims) ----
    uint32_t af[4][4];
    {
        const uint32_t qa = smem_u32(KV[0][0]);
        const uint32_t q_off = (uint32_t)((wid * 16 + (matid & 1) * 8 + lr) * QKV_PITCH
                                          + (matid >> 1) * 16);
        #pragma unroll
        for (int ks = 0; ks < 4; ks++)
            ldsm_x4(af[ks], qa + q_off + ks * 32);
    }
    __syncthreads();   // Q frags extracted; KV[0] free for kt=0

    // ldmatrix per-lane offsets for K (non-trans) and V (trans)
    const uint32_t k_off = (uint32_t)(((matid >> 1) * 8 + lr) * QKV_PITCH + (matid & 1) * 16);
    const uint32_t v_off = (uint32_t)(((matid & 1) * 8 + lr) * QKV_PITCH + (matid >> 1) * 16);

    // ---- issue K/V tile kt into stage s ----
    const __half* kb0 = qkv + (size_t)(b * TT) * H3 + HH + h * HS;
    auto issue = [&](int kt, int s) {
        const __half* kb = kb0 + (size_t)(kt * 64) * H3;
        const __half* vb = kb + HH;
        uint32_t kd = smem_u32(KV[s][0]);
        uint32_t vd = smem_u32(KV[s][1]);
        #pragma unroll
        for (int i = 0; i < 4; i++) {
            int idx = tid + i * 128;
            int r = idx >> 3, c = idx & 7;
            cp_async16(kd + r * QKV_PITCH + c * 16, kb + (size_t)r * H3 + c * 8);
        }
        #pragma unroll
        for (int i = 0; i < 4; i++) {
            int idx = tid + i * 128;
            int r = idx >> 3, c = idx & 7;
            cp_async16(vd + r * QKV_PITCH + c * 16, vb + (size_t)r * H3 + c * 8);
        }
        CP_COMMIT();
    };
    issue(0, 0);

    float O[8][4];
    #pragma unroll
    for (int nt = 0; nt < 8; nt++)
        #pragma unroll
        for (int r = 0; r < 4; r++) O[nt][r] = 0.f;
    float m0 = -INFINITY, m1 = -INFINITY, l0 = 0.f, l1 = 0.f;
    const int row0 = qs + wid * 16 + g;
    const int row1 = row0 + 8;

    for (int kt = 0; kt <= qt; kt++) {
        CP_WAIT0();          // tile kt resident
        __syncthreads();     // all warps past previous compute -> other stage free
        if (kt < qt) issue(kt + 1, (kt + 1) & 1);

        const uint32_t kbase = smem_u32(KV[kt & 1][0]);
        const uint32_t vbase = smem_u32(KV[kt & 1][1]);

        // ---- S = Q @ K^T ----
        float S[8][4];
        #pragma unroll
        for (int nt = 0; nt < 8; nt++)
            #pragma unroll
            for (int r = 0; r < 4; r++) S[nt][r] = 0.f;
        #pragma unroll
        for (int ks = 0; ks < 4; ks++) {      // dims k16 steps
            uint32_t bf[8][2];
            #pragma unroll
            for (int np = 0; np < 4; np++) {  // key-tile pairs
                uint32_t t[4];
                ldsm_x4(t, kbase + k_off + np * (16 * QKV_PITCH) + ks * 32);
                bf[2 * np][0] = t[0]; bf[2 * np][1] = t[1];
                bf[2 * np + 1][0] = t[2]; bf[2 * np + 1][1] = t[3];
            }
            #pragma unroll
            for (int nt = 0; nt < 8; nt++)
                mma16816(S[nt], af[ks], bf[nt]);
        }

        // ---- scale 1/8 in f32, then causal mask on diagonal tile ----
        #pragma unroll
        for (int nt = 0; nt < 8; nt++) {
            S[nt][0] *= 0.125f; S[nt][1] *= 0.125f;
            S[nt][2] *= 0.125f; S[nt][3] *= 0.125f;
        }
        if (kt == qt) {
            #pragma unroll
            for (int nt = 0; nt < 8; nt++) {
                int c0 = kt * 64 + nt * 8 + 2 * tig;
                if (c0     > row0) S[nt][0] = -INFINITY;
                if (c0 + 1 > row0) S[nt][1] = -INFINITY;
                if (c0     > row1) S[nt][2] = -INFINITY;
                if (c0 + 1 > row1) S[nt][3] = -INFINITY;
            }
        }

        // ---- Online softmax (f32) ----
        float tm0 = -INFINITY, tm1 = -INFINITY;
        #pragma unroll
        for (int nt = 0; nt < 8; nt++) {
            tm0 = fmaxf(tm0, fmaxf(S[nt][0], S[nt][1]));
            tm1 = fmaxf(tm1, fmaxf(S[nt][2], S[nt][3]));
        }
        tm0 = fmaxf(tm0, __shfl_xor_sync(0xffffffffu, tm0, 1));
        tm0 = fmaxf(tm0, __shfl_xor_sync(0xffffffffu, tm0, 2));
        tm1 = fmaxf(tm1, __shfl_xor_sync(0xffffffffu, tm1, 1));
        tm1 = fmaxf(tm1, __shfl_xor_sync(0xffffffffu, tm1, 2));

        float mn0 = fmaxf(m0, tm0), mn1 = fmaxf(m1, tm1);
        float al0 = __expf(m0 - mn0), al1 = __expf(m1 - mn1);
        m0 = mn0; m1 = mn1;

        float rs0 = 0.f, rs1 = 0.f;
        #pragma unroll
        for (int nt = 0; nt < 8; nt++) {
            S[nt][0] = __expf(S[nt][0] - mn0);
            S[nt][1] = __expf(S[nt][1] - mn0);
            S[nt][2] = __expf(S[nt][2] - mn1);
            S[nt][3] = __expf(S[nt][3] - mn1);
            rs0 += S[nt][0] + S[nt][1];
            rs1 += S[nt][2] + S[nt][3];
        }
        rs0 += __shfl_xor_sync(0xffffffffu, rs0, 1);
        rs0 += __shfl_xor_sync(0xffffffffu, rs0, 2);
        rs1 += __shfl_xor_sync(0xffffffffu, rs1, 1);
        rs1 += __shfl_xor_sync(0xffffffffu, rs1, 2);
        l0 = l0 * al0 + rs0;
        l1 = l1 * al1 + rs1;

        #pragma unroll
        for (int nt = 0; nt < 8; nt++) {
            O[nt][0] *= al0; O[nt][1] *= al0;
            O[nt][2] *= al1; O[nt][3] *= al1;
        }

        // ---- O += P @ V : P A-frags are direct packs of C-frag (no shfl) ----
        #pragma unroll
        for (int ks = 0; ks < 4; ks++) {      // key k16 steps = S tiles 2ks,2ks+1
            uint32_t a[4];
            a[0] = pack_h2(S[2 * ks][0],     S[2 * ks][1]);
            a[1] = pack_h2(S[2 * ks][2],     S[2 * ks][3]);
            a[2] = pack_h2(S[2 * ks + 1][0], S[2 * ks + 1][1]);
            a[3] = pack_h2(S[2 * ks + 1][2], S[2 * ks + 1][3]);
            uint32_t bf[8][2];
            #pragma unroll
            for (int np = 0; np < 4; np++) {  // dim-tile pairs
                uint32_t t[4];
                ldsm_x4_t(t, vbase + v_off + ks * (16 * QKV_PITCH) + np * 32);
                bf[2 * np][0] = t[0]; bf[2 * np][1] = t[1];
                bf[2 * np + 1][0] = t[2]; bf[2 * np + 1][1] = t[3];
            }
            #pragma unroll
            for (int nt = 0; nt < 8; nt++)
                mma16816(O[nt], a, bf[nt]);
        }
    }

    // ---- Epilogue: normalize, store fp16 ----
    const float inv0 = 1.f / l0;
    const float inv1 = 1.f / l1;
    __half* o0p = att + (size_t)(b * TT + row0) * HH + h * HS;
    __half* o1p = att + (size_t)(b * TT + row1) * HH + h * HS;
    #pragma unroll
    for (int nt = 0; nt < 8; nt++) {
        int c = nt * 8 + 2 * tig;
        *(uint32_t*)(o0p + c) = pack_h2(O[nt][0] * inv0, O[nt][1] * inv0);
        *(uint32_t*)(o1p + c) = pack_h2(O[nt][2] * inv1, O[nt][3] * inv1);
    }
}

// ---------------------------------------------------------------------------
// Launch
// ---------------------------------------------------------------------------
extern "C" void kernel_launch(void* const* d_in, const int* in_sizes, int n_in,
                              void* d_out, int out_size)
{
    const float* x      = (const float*)d_in[0];   // [8,1024,768]
    const float* W_attn = (const float*)d_in[1];   // [768,2304]
    const float* b_attn = (const float*)d_in[2];   // [2304]
    const float* W_proj = (const float*)d_in[3];   // [768,768]
    const float* b_proj = (const float*)d_in[4];   // [768]
    float* out = (float*)d_out;                    // [8,1024,768]

    __half *qkvh, *atth, *xh, *wah, *wph;
    cudaGetSymbolAddress((void**)&qkvh, g_qkvh);
    cudaGetSymbolAddress((void**)&atth, g_atth);
    cudaGetSymbolAddress((void**)&xh,   g_xh);
    cudaGetSymbolAddress((void**)&wah,  g_wah);
    cudaGetSymbolAddress((void**)&wph,  g_wph);

    cudaFuncSetAttribute(gemm_f16_kernel,
                         cudaFuncAttributeMaxDynamicSharedMemorySize, GEMM_SMEM);

    // 0) Convert operands to fp16 (~6us total)
    f32_to_f16_kernel<<<592, 256>>>(x,      xh,  (MROWS * HH) / 8);
    f32_to_f16_kernel<<<592, 256>>>(W_attn, wah, (HH * H3) / 8);
    f32_to_f16_kernel<<<592, 256>>>(W_proj, wph, (HH * HH) / 8);

    // 1) QKV projection -> fp16 qkv
    {
        dim3 grid(H3 / 128, MROWS / 128);
        gemm_f16_kernel<<<grid, 256, GEMM_SMEM>>>(xh, wah, b_attn, qkvh,
                                                  MROWS, H3, HH, 1);
    }
    // 2) Causal attention -> fp16 att
    {
        dim3 grid(TT / 64, NH, BB);
        attn_f16_kernel<<<grid, 128>>>(qkvh, atth);
    }
    // 3) Output projection -> f32 out
    {
        dim3 grid(HH / 128, MROWS / 128);
        gemm_f16_kernel<<<grid, 256, GEMM_SMEM>>>(atth, wph, b_proj, out,
                                                  MROWS, HH, HH, 0);
    }
}